// round 11
// baseline (speedup 1.0000x reference)
#include <cuda_runtime.h>
#include <math.h>

#define N_NODES   20000
#define NODE_DIM  128
#define D_SPH     480
#define D_TOT     608
#define HC        32
#define HID       64

// ------------------- device scratch (static, no allocation) -------------------
__device__ float g_xt[D_TOT * N_NODES];   // feature-major transposed inputs
__device__ float g_A6[HID * 6 * HC];      // folded Wm2:  [h][k6][u]
__device__ float g_bA6[6 * HC];           // folded bm2:  [k6][u]
__device__ float g_C222p[5 * 15];         // packed symmetric C222: [r][pair]
__device__ float g_z[HID * N_NODES];      // silu MLP hidden, feature-major
__device__ float g_g[6 * HC * N_NODES];   // per-node path weights, feature-major

// ============== init: fold Wm2 (blocks 0..97), zero + C222 (block 98) ==============
__global__ void k_init(const float* __restrict__ Wm2, const float* __restrict__ bm2,
                       const float* __restrict__ P0, const float* __restrict__ P2,
                       float* __restrict__ out)
{
    if (blockIdx.x == 98) {
        int tid = threadIdx.x;
        for (int i = tid; i < 2304; i += 128) out[i] = 0.f;
        if (tid < 32) {
            const float s2 = 0.70710678118654752f;
            const float s6 = 0.40824829046386302f;
            bool act = tid < 25;
            int i = act ? (tid / 5) : 0;
            int j = act ? (tid % 5) : 0;

            float Qi[9], Qj[9];
            #pragma unroll
            for (int e = 0; e < 9; e++) { Qi[e] = 0.f; Qj[e] = 0.f; }
            if      (i == 0) { Qi[1] = s2;  Qi[3] = s2; }
            else if (i == 1) { Qi[5] = s2;  Qi[7] = s2; }
            else if (i == 2) { Qi[0] = -s6; Qi[4] = -s6; Qi[8] = 2.f * s6; }
            else if (i == 3) { Qi[2] = s2;  Qi[6] = s2; }
            else             { Qi[0] = s2;  Qi[4] = -s2; }
            if      (j == 0) { Qj[1] = s2;  Qj[3] = s2; }
            else if (j == 1) { Qj[5] = s2;  Qj[7] = s2; }
            else if (j == 2) { Qj[0] = -s6; Qj[4] = -s6; Qj[8] = 2.f * s6; }
            else if (j == 3) { Qj[2] = s2;  Qj[6] = s2; }
            else             { Qj[0] = s2;  Qj[4] = -s2; }

            float M[9];
            #pragma unroll
            for (int a = 0; a < 3; a++)
                #pragma unroll
                for (int d = 0; d < 3; d++) {
                    float m = 0.f;
                    #pragma unroll
                    for (int b = 0; b < 3; b++) m += Qi[a * 3 + b] * Qj[d * 3 + b];
                    M[a * 3 + d] = m;
                }
            float S[9];
            #pragma unroll
            for (int a = 0; a < 3; a++)
                #pragma unroll
                for (int d = 0; d < 3; d++)
                    S[a * 3 + d] = 0.5f * (M[a * 3 + d] + M[d * 3 + a]);
            float tr3 = (S[0] + S[4] + S[8]) * (1.f / 3.f);
            S[0] -= tr3; S[4] -= tr3; S[8] -= tr3;

            float C[5];
            C[0] = s2 * (S[1] + S[3]);
            C[1] = s2 * (S[5] + S[7]);
            C[2] = -s6 * S[0] - s6 * S[4] + 2.f * s6 * S[8];
            C[3] = s2 * (S[2] + S[6]);
            C[4] = s2 * S[0] - s2 * S[4];

            float sloc = 0.f;
            if (act) {
                #pragma unroll
                for (int r = 0; r < 5; r++) sloc += C[r] * C[r];
            }
            #pragma unroll
            for (int off = 16; off > 0; off >>= 1)
                sloc += __shfl_xor_sync(0xffffffffu, sloc, off);
            float sc = sqrtf(5.f / sloc);

            if (act && i <= j) {
                int t = 5 * i - (i * (i - 1)) / 2 + (j - i);
                float f = (i == j) ? sc : 2.f * sc;
                #pragma unroll
                for (int r = 0; r < 5; r++) g_C222p[r * 15 + t] = C[r] * f;
            }
        }
        return;
    }

    int idx = blockIdx.x * 128 + threadIdx.x;
    const int KP[6] = {0, 2, 6, 1, 4, 8};
    const int PO[6] = {0, 32, 64, 0, 32, 96};
    if (idx < HID * 6 * HC) {
        int u  = idx & 31;
        int k6 = (idx >> 5) % 6;
        int h  = idx / 192;
        const float* p = ((k6 < 3) ? P0 : P2) + PO[k6];
        const float* w = Wm2 + h * 9216 + (KP[k6] * 32 + u) * 32;
        float s = 0.f;
        #pragma unroll
        for (int j = 0; j < 32; j++) s += p[j] * w[j];
        if (k6 == 3) {
            const float* p5 = P2 + 64;
            const float* w5 = Wm2 + h * 9216 + (5 * 32 + u) * 32;
            #pragma unroll
            for (int j = 0; j < 32; j++) s += p5[j] * w5[j];
        }
        g_A6[h * 192 + k6 * 32 + u] = s;
    } else if (idx < HID * 6 * HC + 6 * HC) {
        int t  = idx - HID * 6 * HC;
        int u  = t & 31;
        int k6 = t >> 5;
        const float* p = ((k6 < 3) ? P0 : P2) + PO[k6];
        const float* b = bm2 + (KP[k6] * 32 + u) * 32;
        float s = 0.f;
        #pragma unroll
        for (int j = 0; j < 32; j++) s += p[j] * b[j];
        if (k6 == 3) {
            const float* p5 = P2 + 64;
            const float* b5 = bm2 + (5 * 32 + u) * 32;
            #pragma unroll
            for (int j = 0; j < 32; j++) s += p5[j] * b5[j];
        }
        g_bA6[k6 * 32 + u] = s;
    }
}

// ------------------------------ transpose inputs ------------------------------
__global__ void k_transpose(const float* __restrict__ xs, const float* __restrict__ xsph)
{
    __shared__ float tile[32][33];
    int fx0 = blockIdx.x * 32;
    int n0  = blockIdx.y * 32;
    int tx = threadIdx.x, ty = threadIdx.y;
    #pragma unroll
    for (int r = 0; r < 4; r++) {
        int nn = n0 + ty + r * 8;
        int ff = fx0 + tx;
        float v = (ff < NODE_DIM) ? xs[nn * NODE_DIM + ff]
                                  : xsph[nn * D_SPH + (ff - NODE_DIM)];
        tile[ty + r * 8][tx] = v;
    }
    __syncthreads();
    #pragma unroll
    for (int r = 0; r < 4; r++) {
        int ff = fx0 + ty + r * 8;
        g_xt[ff * N_NODES + n0 + tx] = tile[tx][ty + r * 8];
    }
}

// ========================= kernel 1: z = silu(xs@Wm1+bm1) =========================
// 128 thr = 16 node-pairs (32 nodes) x 8 output-eighths. grid 625.
__global__ void __launch_bounds__(128) k_z(
    const float* __restrict__ Wm1, const float* __restrict__ bm1)
{
    __shared__ float sW[NODE_DIM * HID];   // 32 KB
    __shared__ float sb[HID];
    int tid = threadIdx.x;
    for (int i = tid; i < NODE_DIM * HID; i += 128) sW[i] = Wm1[i];
    if (tid < HID) sb[tid] = bm1[tid];
    __syncthreads();

    int pair = tid & 15;
    int q    = tid >> 4;               // 0..7, 8 outputs each
    int n0   = blockIdx.x * 32 + pair * 2;   // grid*32 == 20000 exactly

    float acc[2][8];
    #pragma unroll
    for (int j = 0; j < 8; j++) { acc[0][j] = sb[q * 8 + j]; acc[1][j] = acc[0][j]; }

    const float* xp = g_xt + n0;
    #pragma unroll 4
    for (int i = 0; i < NODE_DIM; i++) {
        float x0 = xp[i * N_NODES];
        float x1 = xp[i * N_NODES + 1];
        const float4* wr = (const float4*)(sW + i * HID + q * 8);
        float4 wa = wr[0], wb = wr[1];
        acc[0][0] += x0 * wa.x; acc[0][1] += x0 * wa.y; acc[0][2] += x0 * wa.z; acc[0][3] += x0 * wa.w;
        acc[0][4] += x0 * wb.x; acc[0][5] += x0 * wb.y; acc[0][6] += x0 * wb.z; acc[0][7] += x0 * wb.w;
        acc[1][0] += x1 * wa.x; acc[1][1] += x1 * wa.y; acc[1][2] += x1 * wa.z; acc[1][3] += x1 * wa.w;
        acc[1][4] += x1 * wb.x; acc[1][5] += x1 * wb.y; acc[1][6] += x1 * wb.z; acc[1][7] += x1 * wb.w;
    }
    float* zp = g_z + (q * 8) * N_NODES + n0;
    #pragma unroll
    for (int j = 0; j < 8; j++) {
        float x0 = acc[0][j], x1 = acc[1][j];
        zp[j * N_NODES]     = x0 / (1.f + __expf(-x0));
        zp[j * N_NODES + 1] = x1 / (1.f + __expf(-x1));
    }
}

// ========================= kernel 2: g = bA + z @ A6 =========================
// 128 thr = 16 node-pairs (32 nodes) x 8 chunks-of-24 outputs. grid 625.
// dynamic smem: A6[12288] | bA[192] = 49.9 KB -> 4 blocks/SM
#define G_SMEM ((12288 + 192) * 4)

__global__ void __launch_bounds__(128) k_g()
{
    extern __shared__ float sm[];
    float* sA6 = sm;             // 12288
    float* sbA = sm + 12288;     // 192
    int tid = threadIdx.x;

    for (int i = tid; i < 12288; i += 128) sA6[i] = g_A6[i];
    for (int i = tid; i < 192;   i += 128) sbA[i] = g_bA6[i];
    __syncthreads();

    int pair = tid & 15;
    int c    = tid >> 4;               // 0..7, 24 outputs each
    int n0   = blockIdx.x * 32 + pair * 2;

    float gg[2][24];
    #pragma unroll
    for (int j = 0; j < 24; j++) { gg[0][j] = sbA[c * 24 + j]; gg[1][j] = gg[0][j]; }

    const float* zp = g_z + n0;
    #pragma unroll 2
    for (int h = 0; h < HID; h++) {
        float z0 = zp[h * N_NODES];
        float z1 = zp[h * N_NODES + 1];
        const float4* ar = (const float4*)(sA6 + h * 192 + c * 24);
        #pragma unroll
        for (int p = 0; p < 6; p++) {
            float4 av = ar[p];
            gg[0][p * 4 + 0] += z0 * av.x; gg[1][p * 4 + 0] += z1 * av.x;
            gg[0][p * 4 + 1] += z0 * av.y; gg[1][p * 4 + 1] += z1 * av.y;
            gg[0][p * 4 + 2] += z0 * av.z; gg[1][p * 4 + 2] += z1 * av.z;
            gg[0][p * 4 + 3] += z0 * av.w; gg[1][p * 4 + 3] += z1 * av.w;
        }
    }
    float* gp = g_g + (c * 24) * N_NODES + n0;
    #pragma unroll
    for (int j = 0; j < 24; j++) {
        gp[j * N_NODES]     = gg[0][j];
        gp[j * N_NODES + 1] = gg[1][j];
    }
}

// ========================= kernel 3: projections + paths + epilogue =========================
// 256 thr = 32 nodes x 8 chunks-of-4 channels (cu warp-uniform). grid 625.
__global__ void __launch_bounds__(256, 3) k_combine(
    const float* __restrict__ W0e, const float* __restrict__ W1o,
    const float* __restrict__ W2e, const int* __restrict__ batch,
    float* __restrict__ out)
{
    __shared__ float sW0[4096];
    __shared__ float sW1[2048];
    __shared__ float sW2[1024];
    __shared__ float sC[80];
    __shared__ float sRed[8 * 32 * 6];
    int tid = threadIdx.x;

    for (int i = tid; i < 4096; i += 256) sW0[i] = W0e[i] * 0.08838834764831845f;  // 1/sqrt(128)
    for (int i = tid; i < 2048; i += 256) sW1[i] = W1o[i] * 0.125f;                // 1/sqrt(64)
    for (int i = tid; i < 1024; i += 256) sW2[i] = W2e[i] * 0.17677669529663689f;  // 1/sqrt(32)
    for (int i = tid; i < 75;   i += 256) sC[i]  = g_C222p[i];
    __syncthreads();

    int nloc = tid & 31;
    int cu   = tid >> 5;               // warp-uniform, 0..7
    int u0   = cu * 4;
    int node = blockIdx.x * 32 + nloc;

    const float S2 = 0.70710678118654752f;
    const float S6 = 0.40824829046386302f;
    float sph0 = 0.f;
    float y2[5] = {0.f, 0.f, 0.f, 0.f, 0.f};

    {
        const float* xp0 = g_xt + 128 * N_NODES + node;
        const float* xp1 = g_xt + 256 * N_NODES + node;
        const float* xp2 = g_xt + 448 * N_NODES + node;

        // a[j] = h0 channels u0..u0+3
        float a[4] = {0.f, 0.f, 0.f, 0.f};
        #pragma unroll 4
        for (int i = 0; i < 128; i++) {
            float xv = xp0[i * N_NODES];
            float4 w = *(const float4*)(sW0 + i * HC + u0);
            a[0] += xv * w.x; a[1] += xv * w.y; a[2] += xv * w.z; a[3] += xv * w.w;
        }

        // b[j][d]
        float b[4][3];
        #pragma unroll
        for (int j = 0; j < 4; j++) { b[j][0] = 0.f; b[j][1] = 0.f; b[j][2] = 0.f; }
        #pragma unroll 4
        for (int i = 0; i < 64; i++) {
            float x0v = xp1[(i * 3 + 0) * N_NODES];
            float x1v = xp1[(i * 3 + 1) * N_NODES];
            float x2v = xp1[(i * 3 + 2) * N_NODES];
            float4 w = *(const float4*)(sW1 + i * HC + u0);
            float wv[4] = {w.x, w.y, w.z, w.w};
            #pragma unroll
            for (int j = 0; j < 4; j++) {
                b[j][0] += x0v * wv[j];
                b[j][1] += x1v * wv[j];
                b[j][2] += x2v * wv[j];
            }
        }

        // c[j][r]
        float c[4][5];
        #pragma unroll
        for (int j = 0; j < 4; j++)
            #pragma unroll
            for (int r = 0; r < 5; r++) c[j][r] = 0.f;
        #pragma unroll 2
        for (int i = 0; i < 32; i++) {
            float xv[5];
            #pragma unroll
            for (int r = 0; r < 5; r++) xv[r] = xp2[(i * 5 + r) * N_NODES];
            float4 w = *(const float4*)(sW2 + i * HC + u0);
            float wv[4] = {w.x, w.y, w.z, w.w};
            #pragma unroll
            for (int j = 0; j < 4; j++)
                #pragma unroll
                for (int r = 0; r < 5; r++) c[j][r] += xv[r] * wv[j];
        }

        // combine per channel
        #pragma unroll
        for (int j = 0; j < 4; j++) {
            const float* gp = g_g + (u0 + j) * N_NODES + node;
            float g0  = gp[0];
            float g1  = gp[32 * N_NODES];
            float g2  = gp[64 * N_NODES];
            float g15 = gp[96 * N_NODES];
            float g4  = gp[128 * N_NODES];
            float g8  = gp[160 * N_NODES];

            float au = a[j];
            float b0 = b[j][0], b1 = b[j][1], b2 = b[j][2];
            float c0 = c[j][0], c1 = c[j][1], c2 = c[j][2], c3 = c[j][3], c4 = c[j][4];
            float bb = b0 * b0 + b1 * b1 + b2 * b2;
            float cc = c0 * c0 + c1 * c1 + c2 * c2 + c3 * c3 + c4 * c4;
            sph0 += g0 * (au * au)
                  + g1 * bb * 0.57735026918962576f
                  + g2 * cc * 0.44721359549995794f;
            y2[0] += g15 * (au * c0);
            y2[1] += g15 * (au * c1);
            y2[2] += g15 * (au * c2);
            y2[3] += g15 * (au * c3);
            y2[4] += g15 * (au * c4);
            y2[0] += g4 * (2.f * S2 * b0 * b1);
            y2[1] += g4 * (2.f * S2 * b1 * b2);
            y2[2] += g4 * (S6 * (2.f * b2 * b2 - b0 * b0 - b1 * b1));
            y2[3] += g4 * (2.f * S2 * b0 * b2);
            y2[4] += g4 * (S2 * (b0 * b0 - b1 * b1));
            float ccp[15] = {c0*c0, c0*c1, c0*c2, c0*c3, c0*c4,
                             c1*c1, c1*c2, c1*c3, c1*c4,
                             c2*c2, c2*c3, c2*c4,
                             c3*c3, c3*c4, c4*c4};
            #pragma unroll
            for (int r = 0; r < 5; r++) {
                float v8 = 0.f;
                #pragma unroll
                for (int t = 0; t < 15; t++) v8 += sC[r * 15 + t] * ccp[t];
                y2[r] += g8 * v8;
            }
        }
    }

    // cross-chunk reduction in smem
    float* rp = sRed + (cu * 32 + nloc) * 6;
    rp[0] = sph0;
    rp[1] = y2[0]; rp[2] = y2[1]; rp[3] = y2[2]; rp[4] = y2[3]; rp[5] = y2[4];
    __syncthreads();

    if (tid < 32) {
        int nn = blockIdx.x * 32 + tid;
        float v[6];
        #pragma unroll
        for (int t = 0; t < 6; t++) {
            float s = 0.f;
            #pragma unroll
            for (int k = 0; k < 8; k++) s += sRed[(k * 32 + tid) * 6 + t];
            v[t] = s;
        }
        float s0 = v[0] * 0.018042195912175804f;   // 1/sqrt(3072)
        float w0 = v[1] * 0.015625f;               // 1/64
        float w1 = v[2] * 0.015625f;
        float w2 = v[3] * 0.015625f;
        float w3 = v[4] * 0.015625f;
        float w4 = v[5] * 0.015625f;

        float d   = s0 * 0.57735026918962576f;
        float t00 = d - S6 * w2 + S2 * w4;
        float t11 = d - S6 * w2 - S2 * w4;
        float t22 = d + 2.f * S6 * w2;
        float t01 = S2 * w0;
        float t12 = S2 * w1;
        float t02 = S2 * w3;

        float* ob = out + batch[nn] * 9;
        atomicAdd(ob + 4, t00);
        atomicAdd(ob + 8, t11);
        atomicAdd(ob + 0, t22);
        atomicAdd(ob + 5, t01);
        atomicAdd(ob + 7, t01);
        atomicAdd(ob + 6, t12);
        atomicAdd(ob + 2, t12);
        atomicAdd(ob + 3, t02);
        atomicAdd(ob + 1, t02);
    }
}

// ------------------------------ launcher ------------------------------
extern "C" void kernel_launch(void* const* d_in, const int* in_sizes, int n_in,
                              void* d_out, int out_size)
{
    const float* x_scalar = (const float*)d_in[0];
    const float* x_sph    = (const float*)d_in[1];
    const int*   batch    = (const int*)  d_in[2];
    const float* W0e      = (const float*)d_in[3];
    const float* W1o      = (const float*)d_in[4];
    const float* W2e      = (const float*)d_in[5];
    const float* Wm1      = (const float*)d_in[6];
    const float* bm1      = (const float*)d_in[7];
    const float* Wm2      = (const float*)d_in[8];
    const float* bm2      = (const float*)d_in[9];
    const float* P0       = (const float*)d_in[10];
    const float* P2       = (const float*)d_in[12];
    float* out = (float*)d_out;

    cudaFuncSetAttribute(k_g, cudaFuncAttributeMaxDynamicSharedMemorySize, G_SMEM);

    int nblk = N_NODES / 32;   // 625

    k_init<<<99, 128>>>(Wm2, bm2, P0, P2, out);
    dim3 tb(32, 8), tg(D_TOT / 32, N_NODES / 32);
    k_transpose<<<tg, tb>>>(x_scalar, x_sph);
    k_z<<<nblk, 128>>>(Wm1, bm1);
    k_g<<<nblk, 128, G_SMEM>>>();
    k_combine<<<nblk, 256>>>(W0e, W1o, W2e, batch, out);
    (void)in_sizes; (void)n_in; (void)out_size;
}

// round 16
// speedup vs baseline: 1.3907x; 1.3907x over previous
#include <cuda_runtime.h>
#include <math.h>

#define N_NODES   20000
#define NODE_DIM  128
#define D_SPH     480
#define D_TOT     608
#define HC        32
#define HID       64
#define NT        256
#define NB        64          // nodes per block

// ------------------- device scratch (static, no allocation) -------------------
__device__ float g_xt[D_TOT * N_NODES];   // feature-major transposed inputs
__device__ float g_A6[HID * 6 * HC];      // folded Wm2:  [h][k6][u]
__device__ float g_bA6[6 * HC];           // folded bm2:  [k6][u]
__device__ float g_C222p[5 * 15];         // packed symmetric C222: [r][pair]
__device__ float g_z[HID * N_NODES];      // silu MLP hidden, feature-major
__device__ float g_g[6 * HC * N_NODES];   // per-node path weights, feature-major

// ============== init: fold Wm2 (blocks 0..97), zero + C222 (block 98) ==============
__global__ void k_init(const float* __restrict__ Wm2, const float* __restrict__ bm2,
                       const float* __restrict__ P0, const float* __restrict__ P2,
                       float* __restrict__ out)
{
    if (blockIdx.x == 98) {
        int tid = threadIdx.x;
        for (int i = tid; i < 2304; i += 128) out[i] = 0.f;
        if (tid < 32) {
            const float s2 = 0.70710678118654752f;
            const float s6 = 0.40824829046386302f;
            bool act = tid < 25;
            int i = act ? (tid / 5) : 0;
            int j = act ? (tid % 5) : 0;

            float Qi[9], Qj[9];
            #pragma unroll
            for (int e = 0; e < 9; e++) { Qi[e] = 0.f; Qj[e] = 0.f; }
            if      (i == 0) { Qi[1] = s2;  Qi[3] = s2; }
            else if (i == 1) { Qi[5] = s2;  Qi[7] = s2; }
            else if (i == 2) { Qi[0] = -s6; Qi[4] = -s6; Qi[8] = 2.f * s6; }
            else if (i == 3) { Qi[2] = s2;  Qi[6] = s2; }
            else             { Qi[0] = s2;  Qi[4] = -s2; }
            if      (j == 0) { Qj[1] = s2;  Qj[3] = s2; }
            else if (j == 1) { Qj[5] = s2;  Qj[7] = s2; }
            else if (j == 2) { Qj[0] = -s6; Qj[4] = -s6; Qj[8] = 2.f * s6; }
            else if (j == 3) { Qj[2] = s2;  Qj[6] = s2; }
            else             { Qj[0] = s2;  Qj[4] = -s2; }

            float M[9];
            #pragma unroll
            for (int a = 0; a < 3; a++)
                #pragma unroll
                for (int d = 0; d < 3; d++) {
                    float m = 0.f;
                    #pragma unroll
                    for (int b = 0; b < 3; b++) m += Qi[a * 3 + b] * Qj[d * 3 + b];
                    M[a * 3 + d] = m;
                }
            float S[9];
            #pragma unroll
            for (int a = 0; a < 3; a++)
                #pragma unroll
                for (int d = 0; d < 3; d++)
                    S[a * 3 + d] = 0.5f * (M[a * 3 + d] + M[d * 3 + a]);
            float tr3 = (S[0] + S[4] + S[8]) * (1.f / 3.f);
            S[0] -= tr3; S[4] -= tr3; S[8] -= tr3;

            float C[5];
            C[0] = s2 * (S[1] + S[3]);
            C[1] = s2 * (S[5] + S[7]);
            C[2] = -s6 * S[0] - s6 * S[4] + 2.f * s6 * S[8];
            C[3] = s2 * (S[2] + S[6]);
            C[4] = s2 * S[0] - s2 * S[4];

            float sloc = 0.f;
            if (act) {
                #pragma unroll
                for (int r = 0; r < 5; r++) sloc += C[r] * C[r];
            }
            #pragma unroll
            for (int off = 16; off > 0; off >>= 1)
                sloc += __shfl_xor_sync(0xffffffffu, sloc, off);
            float sc = sqrtf(5.f / sloc);

            if (act && i <= j) {
                int t = 5 * i - (i * (i - 1)) / 2 + (j - i);
                float f = (i == j) ? sc : 2.f * sc;
                #pragma unroll
                for (int r = 0; r < 5; r++) g_C222p[r * 15 + t] = C[r] * f;
            }
        }
        return;
    }

    int idx = blockIdx.x * 128 + threadIdx.x;
    const int KP[6] = {0, 2, 6, 1, 4, 8};
    const int PO[6] = {0, 32, 64, 0, 32, 96};
    if (idx < HID * 6 * HC) {
        int u  = idx & 31;
        int k6 = (idx >> 5) % 6;
        int h  = idx / 192;
        const float* p = ((k6 < 3) ? P0 : P2) + PO[k6];
        const float* w = Wm2 + h * 9216 + (KP[k6] * 32 + u) * 32;
        float s = 0.f;
        #pragma unroll
        for (int j = 0; j < 32; j++) s += p[j] * w[j];
        if (k6 == 3) {
            const float* p5 = P2 + 64;
            const float* w5 = Wm2 + h * 9216 + (5 * 32 + u) * 32;
            #pragma unroll
            for (int j = 0; j < 32; j++) s += p5[j] * w5[j];
        }
        g_A6[h * 192 + k6 * 32 + u] = s;
    } else if (idx < HID * 6 * HC + 6 * HC) {
        int t  = idx - HID * 6 * HC;
        int u  = t & 31;
        int k6 = t >> 5;
        const float* p = ((k6 < 3) ? P0 : P2) + PO[k6];
        const float* b = bm2 + (KP[k6] * 32 + u) * 32;
        float s = 0.f;
        #pragma unroll
        for (int j = 0; j < 32; j++) s += p[j] * b[j];
        if (k6 == 3) {
            const float* p5 = P2 + 64;
            const float* b5 = bm2 + (5 * 32 + u) * 32;
            #pragma unroll
            for (int j = 0; j < 32; j++) s += p5[j] * b5[j];
        }
        g_bA6[k6 * 32 + u] = s;
    }
}

// ------------------------------ transpose inputs ------------------------------
__global__ void k_transpose(const float* __restrict__ xs, const float* __restrict__ xsph)
{
    __shared__ float tile[32][33];
    int fx0 = blockIdx.x * 32;
    int n0  = blockIdx.y * 32;
    int tx = threadIdx.x, ty = threadIdx.y;
    #pragma unroll
    for (int r = 0; r < 4; r++) {
        int nn = n0 + ty + r * 8;
        int ff = fx0 + tx;
        float v = (ff < NODE_DIM) ? xs[nn * NODE_DIM + ff]
                                  : xsph[nn * D_SPH + (ff - NODE_DIM)];
        tile[ty + r * 8][tx] = v;
    }
    __syncthreads();
    #pragma unroll
    for (int r = 0; r < 4; r++) {
        int ff = fx0 + ty + r * 8;
        g_xt[ff * N_NODES + n0 + tx] = tile[tx][ty + r * 8];
    }
}

// ========================= kernel 1: z = silu(xs@Wm1+bm1) =========================
// thread = (node, quarter). 256 thr = 64 nodes x 4 quarters (quarter warp-uniform).
__global__ void __launch_bounds__(NT) k_z(
    const float* __restrict__ Wm1, const float* __restrict__ bm1)
{
    __shared__ float sW[NODE_DIM * HID];   // 32 KB
    __shared__ float sb[HID];
    int tid = threadIdx.x;
    for (int i = tid; i < NODE_DIM * HID; i += NT) sW[i] = Wm1[i];
    if (tid < HID) sb[tid] = bm1[tid];
    __syncthreads();

    int nloc = tid & 63;
    int q    = tid >> 6;             // warp-uniform
    int node = blockIdx.x * NB + nloc;
    if (node >= N_NODES) return;

    float acc[16];
    #pragma unroll
    for (int j = 0; j < 16; j++) acc[j] = sb[q * 16 + j];

    const float* xp = g_xt + node;
    #pragma unroll 4
    for (int i = 0; i < NODE_DIM; i++) {
        float xv = xp[i * N_NODES];
        const float4* wr = (const float4*)(sW + i * HID + q * 16);
        #pragma unroll
        for (int p = 0; p < 4; p++) {
            float4 wv = wr[p];
            acc[p * 4 + 0] += xv * wv.x;
            acc[p * 4 + 1] += xv * wv.y;
            acc[p * 4 + 2] += xv * wv.z;
            acc[p * 4 + 3] += xv * wv.w;
        }
    }
    float* zp = g_z + (q * 16) * N_NODES + node;
    #pragma unroll
    for (int j = 0; j < 16; j++) {
        float x = acc[j];
        zp[j * N_NODES] = x / (1.f + __expf(-x));
    }
}

// ========================= kernel 2: g = bA + z @ A6 =========================
// 384 thr = 32 node-pairs (64 nodes) x 12 chunks-of-16 outputs. grid 313.
// dynamic smem: A6[12288] | bA[192] | ztile[4096] = 66304 B
#define G_NT   384
#define G_SMEM ((12288 + 192 + 4096) * 4)

__global__ void __launch_bounds__(G_NT) k_g()
{
    extern __shared__ float sm[];
    float* sA6 = sm;             // 12288
    float* sbA = sm + 12288;     // 192
    float* szl = sm + 12480;     // 4096 : [h][64 nodes]
    int tid = threadIdx.x;
    int n0b = blockIdx.x * NB;

    for (int i = tid; i < 12288; i += G_NT) sA6[i] = g_A6[i];
    for (int i = tid; i < 192;   i += G_NT) sbA[i] = g_bA6[i];
    for (int i = tid; i < HID * NB; i += G_NT) {
        int h  = i >> 6;
        int nl = i & 63;
        int nn = n0b + nl;
        szl[i] = (nn < N_NODES) ? g_z[h * N_NODES + nn] : 0.f;
    }
    __syncthreads();

    int pair = tid & 31;           // 32 pairs = 64 nodes
    int c    = tid >> 5;           // 0..11, warp-uniform, 16 outputs each
    int n0   = n0b + pair * 2;

    float gg[2][16];
    #pragma unroll
    for (int j = 0; j < 16; j++) { gg[0][j] = sbA[c * 16 + j]; gg[1][j] = gg[0][j]; }

    #pragma unroll 4
    for (int h = 0; h < HID; h++) {
        float2 z2 = *(const float2*)(szl + h * 64 + pair * 2);
        const float4* ar = (const float4*)(sA6 + h * 192 + c * 16);
        #pragma unroll
        for (int p = 0; p < 4; p++) {
            float4 av = ar[p];
            gg[0][p * 4 + 0] += z2.x * av.x; gg[1][p * 4 + 0] += z2.y * av.x;
            gg[0][p * 4 + 1] += z2.x * av.y; gg[1][p * 4 + 1] += z2.y * av.y;
            gg[0][p * 4 + 2] += z2.x * av.z; gg[1][p * 4 + 2] += z2.y * av.z;
            gg[0][p * 4 + 3] += z2.x * av.w; gg[1][p * 4 + 3] += z2.y * av.w;
        }
    }
    if (n0 < N_NODES) {
        #pragma unroll
        for (int j = 0; j < 16; j++) {
            float2 v = make_float2(gg[0][j], gg[1][j]);
            *(float2*)(g_g + (c * 16 + j) * N_NODES + n0) = v;
        }
    }
}

// ========================= kernel 3: projections + paths + epilogue =========================
// thread = (node, 8-channel chunk). chunk warp-uniform. grid 313, 256 thr.
__global__ void __launch_bounds__(NT) k_combine(
    const float* __restrict__ W0e, const float* __restrict__ W1o,
    const float* __restrict__ W2e, const int* __restrict__ batch,
    float* __restrict__ out)
{
    __shared__ float sW0[4096];
    __shared__ float sW1[2048];
    __shared__ float sW2[1024];
    __shared__ float sC[80];
    __shared__ float sRed[4 * NB * 6];
    int tid = threadIdx.x;

    for (int i = tid; i < 4096; i += NT) sW0[i] = W0e[i] * 0.08838834764831845f;  // 1/sqrt(128)
    for (int i = tid; i < 2048; i += NT) sW1[i] = W1o[i] * 0.125f;                // 1/sqrt(64)
    for (int i = tid; i < 1024; i += NT) sW2[i] = W2e[i] * 0.17677669529663689f;  // 1/sqrt(32)
    for (int i = tid; i < 75;   i += NT) sC[i]  = g_C222p[i];
    __syncthreads();

    int nloc = tid & 63;
    int cu   = tid >> 6;             // warp-uniform
    int u0   = cu * 8;
    int node = blockIdx.x * NB + nloc;

    const float S2 = 0.70710678118654752f;
    const float S6 = 0.40824829046386302f;
    float sph0 = 0.f;
    float y2[5] = {0.f, 0.f, 0.f, 0.f, 0.f};

    if (node < N_NODES) {
        const float* xp0 = g_xt + 128 * N_NODES + node;
        const float* xp1 = g_xt + 256 * N_NODES + node;
        const float* xp2 = g_xt + 448 * N_NODES + node;

        // a[j] = h0 channels u0..u0+7
        float a[8];
        #pragma unroll
        for (int j = 0; j < 8; j++) a[j] = 0.f;
        #pragma unroll 4
        for (int i = 0; i < 128; i++) {
            float xv = xp0[i * N_NODES];
            const float4* wr = (const float4*)(sW0 + i * HC + u0);
            float4 wa = wr[0], wb = wr[1];
            a[0] += xv * wa.x; a[1] += xv * wa.y; a[2] += xv * wa.z; a[3] += xv * wa.w;
            a[4] += xv * wb.x; a[5] += xv * wb.y; a[6] += xv * wb.z; a[7] += xv * wb.w;
        }

        // b[j][d]
        float b[8][3];
        #pragma unroll
        for (int j = 0; j < 8; j++) { b[j][0] = 0.f; b[j][1] = 0.f; b[j][2] = 0.f; }
        #pragma unroll 2
        for (int i = 0; i < 64; i++) {
            float x0v = xp1[(i * 3 + 0) * N_NODES];
            float x1v = xp1[(i * 3 + 1) * N_NODES];
            float x2v = xp1[(i * 3 + 2) * N_NODES];
            const float4* wr = (const float4*)(sW1 + i * HC + u0);
            float4 wa = wr[0], wb = wr[1];
            float wv[8] = {wa.x, wa.y, wa.z, wa.w, wb.x, wb.y, wb.z, wb.w};
            #pragma unroll
            for (int j = 0; j < 8; j++) {
                b[j][0] += x0v * wv[j];
                b[j][1] += x1v * wv[j];
                b[j][2] += x2v * wv[j];
            }
        }

        // c[j][r]
        float c[8][5];
        #pragma unroll
        for (int j = 0; j < 8; j++)
            #pragma unroll
            for (int r = 0; r < 5; r++) c[j][r] = 0.f;
        #pragma unroll 2
        for (int i = 0; i < 32; i++) {
            float xv[5];
            #pragma unroll
            for (int r = 0; r < 5; r++) xv[r] = xp2[(i * 5 + r) * N_NODES];
            const float4* wr = (const float4*)(sW2 + i * HC + u0);
            float4 wa = wr[0], wb = wr[1];
            float wv[8] = {wa.x, wa.y, wa.z, wa.w, wb.x, wb.y, wb.z, wb.w};
            #pragma unroll
            for (int j = 0; j < 8; j++)
                #pragma unroll
                for (int r = 0; r < 5; r++) c[j][r] += xv[r] * wv[j];
        }

        // combine per channel (g loaded per-j to bound register pressure)
        #pragma unroll 2
        for (int j = 0; j < 8; j++) {
            const float* gp = g_g + (u0 + j) * N_NODES + node;
            float g0  = gp[0];
            float g1  = gp[32 * N_NODES];
            float g2  = gp[64 * N_NODES];
            float g15 = gp[96 * N_NODES];
            float g4  = gp[128 * N_NODES];
            float g8  = gp[160 * N_NODES];

            float au = a[j];
            float b0 = b[j][0], b1 = b[j][1], b2 = b[j][2];
            float c0 = c[j][0], c1 = c[j][1], c2 = c[j][2], c3 = c[j][3], c4 = c[j][4];
            float bb = b0 * b0 + b1 * b1 + b2 * b2;
            float cc = c0 * c0 + c1 * c1 + c2 * c2 + c3 * c3 + c4 * c4;
            sph0 += g0 * (au * au)
                  + g1 * bb * 0.57735026918962576f
                  + g2 * cc * 0.44721359549995794f;
            y2[0] += g15 * (au * c0);
            y2[1] += g15 * (au * c1);
            y2[2] += g15 * (au * c2);
            y2[3] += g15 * (au * c3);
            y2[4] += g15 * (au * c4);
            y2[0] += g4 * (2.f * S2 * b0 * b1);
            y2[1] += g4 * (2.f * S2 * b1 * b2);
            y2[2] += g4 * (S6 * (2.f * b2 * b2 - b0 * b0 - b1 * b1));
            y2[3] += g4 * (2.f * S2 * b0 * b2);
            y2[4] += g4 * (S2 * (b0 * b0 - b1 * b1));
            float ccp[15] = {c0*c0, c0*c1, c0*c2, c0*c3, c0*c4,
                             c1*c1, c1*c2, c1*c3, c1*c4,
                             c2*c2, c2*c3, c2*c4,
                             c3*c3, c3*c4, c4*c4};
            #pragma unroll
            for (int r = 0; r < 5; r++) {
                float v8 = 0.f;
                #pragma unroll
                for (int t = 0; t < 15; t++) v8 += sC[r * 15 + t] * ccp[t];
                y2[r] += g8 * v8;
            }
        }
    }

    // cross-chunk reduction in smem
    float* rp = sRed + (cu * NB + nloc) * 6;
    rp[0] = sph0;
    rp[1] = y2[0]; rp[2] = y2[1]; rp[3] = y2[2]; rp[4] = y2[3]; rp[5] = y2[4];
    __syncthreads();

    if (tid < NB) {
        int nn = blockIdx.x * NB + tid;
        if (nn < N_NODES) {
            float v[6];
            #pragma unroll
            for (int t = 0; t < 6; t++) {
                v[t] = sRed[(0 * NB + tid) * 6 + t] + sRed[(1 * NB + tid) * 6 + t]
                     + sRed[(2 * NB + tid) * 6 + t] + sRed[(3 * NB + tid) * 6 + t];
            }
            float s0 = v[0] * 0.018042195912175804f;   // 1/sqrt(3072)
            float w0 = v[1] * 0.015625f;               // 1/64
            float w1 = v[2] * 0.015625f;
            float w2 = v[3] * 0.015625f;
            float w3 = v[4] * 0.015625f;
            float w4 = v[5] * 0.015625f;

            float d   = s0 * 0.57735026918962576f;
            float t00 = d - S6 * w2 + S2 * w4;
            float t11 = d - S6 * w2 - S2 * w4;
            float t22 = d + 2.f * S6 * w2;
            float t01 = S2 * w0;
            float t12 = S2 * w1;
            float t02 = S2 * w3;

            float* ob = out + batch[nn] * 9;
            atomicAdd(ob + 4, t00);
            atomicAdd(ob + 8, t11);
            atomicAdd(ob + 0, t22);
            atomicAdd(ob + 5, t01);
            atomicAdd(ob + 7, t01);
            atomicAdd(ob + 6, t12);
            atomicAdd(ob + 2, t12);
            atomicAdd(ob + 3, t02);
            atomicAdd(ob + 1, t02);
        }
    }
}

// ------------------------------ launcher ------------------------------
extern "C" void kernel_launch(void* const* d_in, const int* in_sizes, int n_in,
                              void* d_out, int out_size)
{
    const float* x_scalar = (const float*)d_in[0];
    const float* x_sph    = (const float*)d_in[1];
    const int*   batch    = (const int*)  d_in[2];
    const float* W0e      = (const float*)d_in[3];
    const float* W1o      = (const float*)d_in[4];
    const float* W2e      = (const float*)d_in[5];
    const float* Wm1      = (const float*)d_in[6];
    const float* bm1      = (const float*)d_in[7];
    const float* Wm2      = (const float*)d_in[8];
    const float* bm2      = (const float*)d_in[9];
    const float* P0       = (const float*)d_in[10];
    const float* P2       = (const float*)d_in[12];
    float* out = (float*)d_out;

    cudaFuncSetAttribute(k_g, cudaFuncAttributeMaxDynamicSharedMemorySize, G_SMEM);

    int nblk = (N_NODES + NB - 1) / NB;   // 313

    k_init<<<99, 128>>>(Wm2, bm2, P0, P2, out);
    dim3 tb(32, 8), tg(D_TOT / 32, N_NODES / 32);
    k_transpose<<<tg, tb>>>(x_scalar, x_sph);
    k_z<<<nblk, NT>>>(Wm1, bm1);
    k_g<<<nblk, G_NT, G_SMEM>>>();
    k_combine<<<nblk, NT>>>(W0e, W1o, W2e, batch, out);
    (void)in_sizes; (void)n_in; (void)out_size;
}